// round 16
// baseline (speedup 1.0000x reference)
#include <cuda_runtime.h>
#include <cstdint>

#define NUM_CLASSES 32
#define MAX_DET     100
#define CONF        0.25f
#define IOU_C       0.45f
#define HC          1.4901161193847656e-8f   // 2^-26 = half-ulp(0.45f)
#define BATCH       64
#define ANCHORS     8400
#define NT          512
#define KPT         9
#define HALF        (NT * KPT)               // 4608 anchors per CTA
#define PADDED      (2 * HALF)               // 9216
#define NWARPS      (NT / 32)                // 16
#define GROUPW      (32 * KPT)               // 288 anchors per warp-group (32 groups)
#define NEG_INF_I   ((int)0x80000000)
#define IDX_SENT    0x7FFFFFFF

#define P1_NT       512
#define P1_GRIDX    (PADDED / P1_NT)         // 18

// scratch (allocation-free rule: __device__ globals)
__device__ float4 g_box[BATCH * PADDED];
__device__ float  g_sc [BATCH * PADDED];
__device__ float  g_cls[BATCH * PADDED];

// NMS dynamic smem per CTA: boxes[9216] | cls[9216] | area[9216]
#define SMEM_CLS    (PADDED * 16)
#define SMEM_AREA   (PADDED * 20)
#define SMEM_BYTES  (PADDED * 24)

// ---------------- helpers ----------------
__device__ __forceinline__ uint32_t smem_u32(const void* p) {
    uint32_t a;
    asm("{ .reg .u64 t; cvta.to.shared.u64 t, %1; cvt.u32.u64 %0, t; }" : "=r"(a) : "l"(p));
    return a;
}
__device__ __forceinline__ uint32_t mapa_peer(uint32_t laddr, uint32_t peer) {
    uint32_t r;
    asm("mapa.shared::cluster.u32 %0, %1, %2;" : "=r"(r) : "r"(laddr), "r"(peer));
    return r;
}
__device__ __forceinline__ void st_peer_u64(uint32_t raddr, uint64_t v) {
    asm volatile("st.shared::cluster.u64 [%0], %1;" :: "r"(raddr), "l"(v) : "memory");
}
__device__ __forceinline__ void mbar_init(uint32_t a, uint32_t cnt) {
    asm volatile("mbarrier.init.shared.b64 [%0], %1;" :: "r"(a), "r"(cnt) : "memory");
}
__device__ __forceinline__ void mbar_arrive_rel(uint32_t a) {   // own barrier
    asm volatile("mbarrier.arrive.release.cluster.shared::cta.b64 _, [%0];"
                 :: "r"(a) : "memory");
}
__device__ __forceinline__ void mbar_arrive_peer_rel(uint32_t laddr, uint32_t peer) {
    asm volatile("{\n\t.reg .b32 r;\n\t"
                 "mapa.shared::cluster.u32 r, %0, %1;\n\t"
                 "mbarrier.arrive.release.cluster.shared::cluster.b64 _, [r];\n\t}"
                 :: "r"(laddr), "r"(peer) : "memory");
}
__device__ __forceinline__ void mbar_wait_acq(uint32_t a, uint32_t parity) {
    uint32_t done;
    asm volatile("{\n\t.reg .pred p;\n\t"
                 "mbarrier.try_wait.parity.acquire.cluster.shared::cta.b64 p, [%1], %2;\n\t"
                 "selp.b32 %0, 1, 0, p;\n\t}"
                 : "=r"(done) : "r"(a), "r"(parity) : "memory");
    if (!done) {
        asm volatile("{\n\t.reg .pred P1;\n\t"
                     "WL_%=:\n\t"
                     "mbarrier.try_wait.parity.acquire.cluster.shared::cta.b64 P1, [%0], %1;\n\t"
                     "@P1 bra.uni WD_%=;\n\t"
                     "bra.uni WL_%=;\n\t"
                     "WD_%=:\n\t}"
                     :: "r"(a), "r"(parity) : "memory");
    }
}
#define CLUSTER_ARRIVE() asm volatile("barrier.cluster.arrive.aligned;" ::: "memory")
#define CLUSTER_WAIT()   asm volatile("barrier.cluster.wait.aligned;" ::: "memory")

// packed (key, idx): u64 descending order == (key desc, idx asc)
__device__ __forceinline__ uint64_t pack_ki(int k, int i) {
    return ((uint64_t)(uint32_t)(k ^ 0x80000000) << 32) | (uint32_t)(~i);
}
__device__ __forceinline__ int unpack_k(uint64_t e) { return (int)((uint32_t)(e >> 32) ^ 0x80000000u); }
__device__ __forceinline__ int unpack_i(uint64_t e) { return (int)(~(uint32_t)e); }

// exact reference suppression: does winner (wb, wa) suppress box (cb, cab)?
__device__ __forceinline__ bool sup_test(float4 wb, float wa, float4 cb, float cab) {
    float iy1 = fmaxf(wb.x, cb.x);
    float ix1 = fmaxf(wb.y, cb.y);
    float iy2 = fminf(wb.z, cb.z);
    float ix2 = fminf(wb.w, cb.w);
    float inter = fmaxf(iy2 - iy1, 0.0f) * fmaxf(ix2 - ix1, 0.0f);
    float uni = wa + cab - inter;
    float d = fmaf(-IOU_C, uni, inter);
    return d > uni * HC;     // exact fl(inter/uni) > 0.45f
}

// ---------------- Phase 1: full-chip decode ----------------
__global__ __launch_bounds__(P1_NT)
void decode_kernel(const float* __restrict__ in)
{
    const int a = blockIdx.x * P1_NT + threadIdx.x;   // 0..9215
    const int b = blockIdx.y;
    const size_t o = (size_t)b * PADDED + a;

    if (a < ANCHORS) {
        const float* base = in + (size_t)b * (4 + NUM_CLASSES) * ANCHORS;
        float xc = base[0 * ANCHORS + a];
        float yc = base[1 * ANCHORS + a];
        float w  = base[2 * ANCHORS + a];
        float h  = base[3 * ANCHORS + a];

        float bs = base[4 * ANCHORS + a];
        int   bc = 0;
        #pragma unroll
        for (int c = 1; c < NUM_CLASSES; c++) {
            float v = base[(4 + c) * ANCHORS + a];
            if (v > bs) { bs = v; bc = c; }   // strict > = first max (jnp.argmax)
        }

        float hw = w * 0.5f;
        float hh = h * 0.5f;
        float y1 = fminf(fmaxf(yc - hh, 0.0f), 1.0f);
        float x1 = fminf(fmaxf(xc - hw, 0.0f), 1.0f);
        float y2 = fminf(fmaxf(yc + hh, 0.0f), 1.0f);
        float x2 = fminf(fmaxf(xc + hw, 0.0f), 1.0f);

        g_box[o] = make_float4(y1, x1, y2, x2);
        g_sc[o]  = (bs >= CONF) ? bs : -1.0f;
        g_cls[o] = (float)bc;
    } else {
        g_box[o] = make_float4(0.0f, 0.0f, 0.0f, 0.0f);
        g_sc[o]  = -1.0f;
        g_cls[o] = 0.0f;
    }
}

// ---------------- Phase 2: 2-CTA-cluster NMS, top-5 multi-emit ----------------
__global__ __launch_bounds__(NT, 1) __cluster_dims__(2, 1, 1)
void nms_kernel(float* __restrict__ out)
{
    extern __shared__ char smem[];
    float4* sbox  = reinterpret_cast<float4*>(smem);                 // FULL boxes
    float*  scls  = reinterpret_cast<float*>(smem + SMEM_CLS);       // FULL classes
    float*  sarea = reinterpret_cast<float*>(smem + SMEM_AREA);      // FULL areas

    __shared__ __align__(16) uint64_t s_own [2][3 * NWARPS];  // own warp top-3 (48)
    __shared__ __align__(16) uint64_t s_mail[2][3 * NWARPS];  // peer warp top-3 (48)
    __shared__ uint64_t s_mbar[2];

    const int tid  = threadIdx.x;
    const int lane = tid & 31;
    const int wid  = tid >> 5;
    const unsigned FULL = 0xffffffffu;
    uint32_t rank;
    asm("mov.u32 %0, %%cluster_ctarank;" : "=r"(rank));
    const uint32_t peer = rank ^ 1;
    const int b = blockIdx.x >> 1;

    const uint32_t mb0 = smem_u32(&s_mbar[0]);
    const uint32_t mb1 = smem_u32(&s_mbar[1]);
    const uint32_t pm0 = mapa_peer(smem_u32(&s_mail[0][0]), peer);
    const uint32_t pm1 = mapa_peer(smem_u32(&s_mail[1][0]), peer);

    // count = 32: 16 own-warp arrives + 16 peer-warp arrives -> single sync point
    if (tid == 0) { mbar_init(mb0, 2 * NWARPS); mbar_init(mb1, 2 * NWARPS); }

    // coalesced fill of the FULL arrays (both CTAs replicate); precompute areas
    const float4* gb = g_box + (size_t)b * PADDED;
    const float*  gc = g_cls + (size_t)b * PADDED;
    for (int a = tid; a < PADDED; a += NT) {
        float4 v = gb[a];
        sbox[a] = v;
        scls[a] = gc[a];
        sarea[a] = (v.z - v.x) * (v.w - v.y);   // exact reference area
    }
    __syncthreads();

    CLUSTER_ARRIVE(); CLUSTER_WAIT();        // mbarrier init + smem visible

    // register slice: this CTA owns global anchors [rank*HALF + t*9, +9)
    float ry1[KPT], rx1[KPT], ry2[KPT], rx2[KPT], rsc[KPT];
    const int gbase = (int)rank * HALF + tid * KPT;
    const float* gs = g_sc + (size_t)b * PADDED + gbase;
    int tk1 = NEG_INF_I, ti1 = 0, tk2 = NEG_INF_I, ti2 = 0, tk3 = NEG_INF_I, ti3 = 0;
    #pragma unroll
    for (int k = 0; k < KPT; k++) {
        float4 v = sbox[gbase + k];
        ry1[k] = v.x; rx1[k] = v.y; ry2[k] = v.z; rx2[k] = v.w;
        float sv = gs[k];
        rsc[k] = sv;
        int ik = __float_as_int(sv);
        int gg = gbase + k;
        if (ik > tk1)      { tk3 = tk2; ti3 = ti2; tk2 = tk1; ti2 = ti1; tk1 = ik; ti1 = gg; }
        else if (ik > tk2) { tk3 = tk2; ti3 = ti2; tk2 = ik; ti2 = gg; }
        else if (ik > tk3) { tk3 = ik; ti3 = gg; }
    }

    float* out_boxes = out + (size_t)b * MAX_DET * 4;
    float* out_cls   = out + (size_t)BATCH * MAX_DET * 4 + (size_t)b * MAX_DET;
    float* out_sc    = out + (size_t)BATCH * MAX_DET * 5 + (size_t)b * MAX_DET;
    float* out_nd    = out + (size_t)BATCH * MAX_DET * 6 + b;

    const uint64_t SENTMIN = pack_ki(NEG_INF_I, IDX_SENT);

    int ndet = 0, p = 0, ph0 = 0, ph1 = 0;
    while (ndet < MAX_DET) {
        // ---- Stage B: warp top-3 via 3 redux pop rounds ----
        uint64_t w0e, w1e, w2e;
        {
            int a0k = tk1, a0i = ti1, a1k = tk2, a1i = ti2, a2k = tk3, a2i = ti3;
            #pragma unroll
            for (int r = 0; r < 3; r++) {
                int M = __reduce_max_sync(FULL, a0k);
                int I = __reduce_min_sync(FULL, (a0k == M) ? a0i : IDX_SENT);
                uint64_t e = pack_ki(M, I);
                if (r == 0) w0e = e; else if (r == 1) w1e = e; else w2e = e;
                if (a0k == M && a0i == I) {
                    a0k = a1k; a0i = a1i; a1k = a2k; a1i = a2i;
                    a2k = NEG_INF_I; a2i = IDX_SENT;
                }
            }
        }

        // ---- publish: own smem + peer smem; arrive own + peer (release) ----
        // Parity-2 reuse: rewriting parity-p buffers at pass t is safe — our
        // pass t-1 wait required every warp's t-1 arrive, each program-ordered
        // (via warp-collective redux in stage B/C) after that warp's t-2 reads.
        uint32_t mb = p ? mb1 : mb0;
        if (lane == 0) {
            s_own[p][3 * wid + 0] = w0e;
            s_own[p][3 * wid + 1] = w1e;
            s_own[p][3 * wid + 2] = w2e;
            uint32_t r = (p ? pm1 : pm0) + (uint32_t)(wid * 24);
            st_peer_u64(r,      w0e);
            st_peer_u64(r + 8,  w1e);
            st_peer_u64(r + 16, w2e);
            mbar_arrive_rel(mb);              // own visibility (CTA)
            mbar_arrive_peer_rel(mb, peer);   // peer visibility (cluster)
        }
        mbar_wait_acq(mb, (uint32_t)(p ? ph1 : ph0));   // all 32 arrives
        if (p) ph1 ^= 1; else ph0 ^= 1;

        // ---- Stage C: top-5 of the 96-entry multiset (3 per lane, sorted) ----
        uint64_t E0 = s_own[p][lane];
        uint64_t E1 = (lane < 16) ? s_own[p][lane + 32] : s_mail[p][lane - 16];
        uint64_t E2 = s_mail[p][lane + 16];
        { uint64_t t;
          if (E0 < E1) { t = E0; E0 = E1; E1 = t; }
          if (E1 < E2) { t = E1; E1 = E2; E2 = t; }
          if (E0 < E1) { t = E0; E0 = E1; E1 = t; } }
        int c0k, c0i, c1k, c1i, c2k, c2i, c3k, c3i, c4k, c4i;
        #define CROUND(CK, CI)                                                 \
        {   int k = unpack_k(E0); int i = unpack_i(E0);                        \
            int M = __reduce_max_sync(FULL, k);                                \
            int I = __reduce_min_sync(FULL, (k == M) ? i : IDX_SENT);          \
            CK = M; CI = (M > 0) ? I : 0;                                      \
            if (k == M && i == I) { E0 = E1; E1 = E2; E2 = SENTMIN; }          \
        }
        CROUND(c0k, c0i) CROUND(c1k, c1i) CROUND(c2k, c2i)
        CROUND(c3k, c3i) CROUND(c4k, c4i)
        #undef CROUND

        if (c0k <= 0) break;                  // symmetric data -> uniform break

        // ---- trust (per-group top-3 published): c0..c2 always exact;
        // c3 exact unless g0==g1==g2; c4 exact unless any group 3x in g0..g3.
        int g0 = c0i / GROUPW, g1 = c1i / GROUPW, g2 = c2i / GROUPW, g3 = c3i / GROUPW;
        bool tr3 = !(g0 == g1 && g1 == g2);
        bool tr4 = !((g0 == g1 && g1 == g2) || (g0 == g1 && g1 == g3) ||
                     (g0 == g2 && g2 == g3) || (g1 == g2 && g2 == g3));
        bool v1 = c1k > 0;
        bool v2 = c2k > 0;
        bool v3 = (c3k > 0) && tr3;
        bool v4 = (c4k > 0) && tr4;

        // ---- lane-parallel pairwise suppression tests (10 pairs) ----
        // lane l -> pair (u,t): l0=(0,1) l1=(0,2) l2=(1,2) l3=(0,3) l4=(1,3)
        // l5=(2,3) l6=(0,4) l7=(1,4) l8=(2,4) l9=(3,4); lanes>=10 masked out.
        int tt = 1 + (lane >= 1) + (lane >= 3) + (lane >= 6);
        int uu = lane - ((tt == 2) ? 1 : (tt == 3) ? 3 : (tt == 4) ? 6 : 0);
        int iu = (uu == 0) ? c0i : (uu == 1) ? c1i : (uu == 2) ? c2i : c3i;
        int it = (tt == 1) ? c1i : (tt == 2) ? c2i : (tt == 3) ? c3i : c4i;
        bool deadp;
        {
            float4 bu = sbox[iu]; float au = sarea[iu];
            float4 bt = sbox[it]; float at = sarea[it];
            deadp = sup_test(bu, au, bt, at);
        }
        unsigned supb = __ballot_sync(FULL, deadp) & 0x3FFu;

        // ---- acceptance chain (exact sorted-scan: only ACCEPTED suppress) ----
        int budget = MAX_DET - ndet;          // >= 1
        unsigned acc = 1u; int na = 1;        // c0 always the next ref winner
        bool A1 = v1 && !((supb >> 0) & 1) && (na < budget);
        if (A1) { acc |= 2u; na++; }
        bool A2 = v2 && !(((supb >> 1) & 1) || (A1 && ((supb >> 2) & 1))) && (na < budget);
        if (A2) { acc |= 4u; na++; }
        bool A3 = v3 && !(((supb >> 3) & 1) || (A1 && ((supb >> 4) & 1))
                       || (A2 && ((supb >> 5) & 1))) && (na < budget);
        if (A3) { acc |= 8u; na++; }
        bool A4 = v4 && !(((supb >> 6) & 1) || (A1 && ((supb >> 7) & 1))
                       || (A2 && ((supb >> 8) & 1)) || (A3 && ((supb >> 9) & 1)))
                     && (na < budget);
        if (A4) { acc |= 16u; na++; }

        // ---- emit accepted candidates in order ----
        if (rank == 0 && tid == 0) {
            int q = ndet;
            #define EMIT(BIT, CI, CK)                                          \
            if (acc & (BIT)) {                                                 \
                *reinterpret_cast<float4*>(out_boxes + q * 4) = sbox[CI];      \
                out_cls[q] = scls[CI];                                         \
                out_sc[q]  = __int_as_float(CK);                               \
                q++;                                                           \
            }
            EMIT(1u,  c0i, c0k) EMIT(2u,  c1i, c1k) EMIT(4u,  c2i, c2k)
            EMIT(8u,  c3i, c3k) EMIT(16u, c4i, c4k)
            #undef EMIT
        }

        ndet += na;

        // ---- register scan: suppress vs accepted winners, rebuild top-3 ----
        if (ndet < MAX_DET && tk1 > 0) {      // dead slice -> state stays exact
            #pragma unroll 1
            for (int t = 0; t < 5; t++) {     // uniform branches; 1 body copy
                if (acc & (1u << t)) {
                    int CI = (t == 0) ? c0i : (t == 1) ? c1i : (t == 2) ? c2i
                           : (t == 3) ? c3i : c4i;
                    float4 W = sbox[CI];
                    float WA = sarea[CI];
                    #pragma unroll
                    for (int k = 0; k < KPT; k++) {
                        float ab = sarea[gbase + k];
                        float q1 = fmaxf(W.x, ry1[k]);
                        float q2 = fmaxf(W.y, rx1[k]);
                        float q3 = fminf(W.z, ry2[k]);
                        float q4 = fminf(W.w, rx2[k]);
                        float iv = fmaxf(q3 - q1, 0.0f) * fmaxf(q4 - q2, 0.0f);
                        float u  = WA + ab - iv;
                        float e  = fmaf(-IOU_C, u, iv);
                        bool s = (e > u * HC) || (gbase + k == CI);
                        rsc[k] = s ? -1.0f : rsc[k];
                    }
                }
            }
            int nk1 = NEG_INF_I, ni1 = 0, nk2 = NEG_INF_I, ni2 = 0, nk3 = NEG_INF_I, ni3 = 0;
            #pragma unroll
            for (int k = 0; k < KPT; k++) {
                int ik = __float_as_int(rsc[k]);
                int gg = gbase + k;
                if (ik > nk1)      { nk3 = nk2; ni3 = ni2; nk2 = nk1; ni2 = ni1; nk1 = ik; ni1 = gg; }
                else if (ik > nk2) { nk3 = nk2; ni3 = ni2; nk2 = ik; ni2 = gg; }
                else if (ik > nk3) { nk3 = ik; ni3 = gg; }
            }
            tk1 = nk1; ti1 = ni1; tk2 = nk2; ti2 = ni2; tk3 = nk3; ti3 = ni3;
        }

        p ^= 1;
    }

    // tail zero-fill (out is poisoned; reference emits zeros for !ok slots)
    if (rank == 0) {
        for (int i = ndet + tid; i < MAX_DET; i += NT) {
            out_boxes[i * 4 + 0] = 0.0f;
            out_boxes[i * 4 + 1] = 0.0f;
            out_boxes[i * 4 + 2] = 0.0f;
            out_boxes[i * 4 + 3] = 0.0f;
            out_cls[i] = 0.0f;
            out_sc[i]  = 0.0f;
        }
        if (tid == 0) *out_nd = (float)ndet;
    }

    CLUSTER_ARRIVE(); CLUSTER_WAIT();    // no CTA exits while peer may signal it
}

extern "C" void kernel_launch(void* const* d_in, const int* in_sizes, int n_in,
                              void* d_out, int out_size)
{
    (void)in_sizes; (void)n_in; (void)out_size;
    const float* in = (const float*)d_in[0];
    float* out = (float*)d_out;

    cudaFuncSetAttribute(nms_kernel,
                         cudaFuncAttributeMaxDynamicSharedMemorySize, SMEM_BYTES);

    dim3 g1(P1_GRIDX, BATCH);
    decode_kernel<<<g1, P1_NT>>>(in);
    nms_kernel<<<2 * BATCH, NT, SMEM_BYTES>>>(out);
}